// round 1
// baseline (speedup 1.0000x reference)
#include <cuda_runtime.h>
#include <cuda_bf16.h>
#include <math.h>

#define N_NODES 50000
#define N_EDGES 640000
#define IN_DIM  5
#define HID     128
#define NUM_GRAPHS 512

// ---------------- scratch (no allocations allowed) ----------------
__device__ float g_h0[(size_t)N_NODES * HID];
__device__ float g_h1[(size_t)N_NODES * HID];
__device__ float g_agg[(size_t)N_NODES * HID];
__device__ float g_agg5[(size_t)N_NODES * IN_DIM];
__device__ float g_pool[(size_t)NUM_GRAPHS * HID];
__device__ float g_cnt[NUM_GRAPHS];

// ---------------- zero kernel ----------------
__global__ void zero_kernel(float* __restrict__ p, size_t n4) {
    size_t i = (size_t)blockIdx.x * blockDim.x + threadIdx.x;
    if (i < n4) ((float4*)p)[i] = make_float4(0.f, 0.f, 0.f, 0.f);
}

// ---------------- layer 0: 5-dim scatter ----------------
__global__ void scatter5_kernel(const float* __restrict__ x,
                                const int* __restrict__ ei) {
    int e = blockIdx.x * blockDim.x + threadIdx.x;
    if (e >= N_EDGES) return;
    int s = ei[e];
    int d = ei[N_EDGES + e];
    const float* xs = x + (size_t)s * IN_DIM;
    float* a = g_agg5 + (size_t)d * IN_DIM;
#pragma unroll
    for (int i = 0; i < IN_DIM; i++) atomicAdd(a + i, xs[i]);
}

// ---------------- layer 0: dense (K=5) ----------------
__global__ void layer0_dense_kernel(const float* __restrict__ x,
                                    const float* __restrict__ Wr,
                                    const float* __restrict__ br,
                                    const float* __restrict__ Wt) {
    // 512 threads = 4 nodes per block, 128 outputs each
    int n = blockIdx.x * 4 + (threadIdx.x >> 7);
    int o = threadIdx.x & 127;
    if (n >= N_NODES) return;
    float acc = br[o];
#pragma unroll
    for (int i = 0; i < IN_DIM; i++) {
        acc = fmaf(g_agg5[(size_t)n * IN_DIM + i], Wr[i * HID + o], acc);
        acc = fmaf(x[(size_t)n * IN_DIM + i],     Wt[i * HID + o], acc);
    }
    g_h0[(size_t)n * HID + o] = fmaxf(acc, 0.f);
}

// ---------------- 128-dim edge scatter: 1 warp per edge ----------------
__global__ void scatter128_kernel(const float* __restrict__ h,
                                  const int* __restrict__ ei) {
    int warp = (blockIdx.x * blockDim.x + threadIdx.x) >> 5;
    int lane = threadIdx.x & 31;
    if (warp >= N_EDGES) return;
    int s = ei[warp];
    int d = ei[N_EDGES + warp];
    float4 v = *(const float4*)(h + (size_t)s * HID + lane * 4);
    float* a = g_agg + (size_t)d * HID + lane * 4;
    atomicAdd(a + 0, v.x);
    atomicAdd(a + 1, v.y);
    atomicAdd(a + 2, v.z);
    atomicAdd(a + 3, v.w);
}

// ---------------- fused dense: out = act(agg@W_rel + h@W_root + b) ----------------
// M=50000, N=128, K=128 per phase (2 phases). BM=64, BN=128, BK=16, 256 threads,
// 4x8 register micro-tile per thread.
template <int RELU>
__global__ __launch_bounds__(256)
void fused_dense_kernel(const float* __restrict__ A0,   // agg
                        const float* __restrict__ A1,   // h
                        const float* __restrict__ W0,   // W_rel [128,128]
                        const float* __restrict__ W1,   // W_root [128,128]
                        const float* __restrict__ bias,
                        float* __restrict__ out) {
    __shared__ float As[64][17];
    __shared__ float Bs[16][128];
    const int tid = threadIdx.x;
    const int tx = tid & 15;   // col group: cols tx*8..tx*8+7
    const int ty = tid >> 4;   // row group: rows ty*4..ty*4+3
    const int row0 = blockIdx.x * 64;
    float acc[4][8];
#pragma unroll
    for (int i = 0; i < 4; i++)
#pragma unroll
        for (int j = 0; j < 8; j++) acc[i][j] = 0.f;

#pragma unroll
    for (int phase = 0; phase < 2; phase++) {
        const float* A = phase ? A1 : A0;
        const float* W = phase ? W1 : W0;
        for (int k0 = 0; k0 < HID; k0 += 16) {
            // --- load A tile 64x16 (one float4 per thread) ---
            {
                int r = tid >> 2;
                int c = (tid & 3) * 4;
                int gr = row0 + r;
                float4 v = make_float4(0.f, 0.f, 0.f, 0.f);
                if (gr < N_NODES)
                    v = *(const float4*)(A + (size_t)gr * HID + k0 + c);
                As[r][c + 0] = v.x;
                As[r][c + 1] = v.y;
                As[r][c + 2] = v.z;
                As[r][c + 3] = v.w;
            }
            // --- load B tile 16x128 (two float4 per thread) ---
#pragma unroll
            for (int rep = 0; rep < 2; rep++) {
                int li = tid + rep * 256;      // 0..511
                int r = li >> 5;               // 0..15
                int c = (li & 31) * 4;         // 0..124
                *(float4*)&Bs[r][c] = *(const float4*)(W + (size_t)(k0 + r) * HID + c);
            }
            __syncthreads();
#pragma unroll
            for (int k = 0; k < 16; k++) {
                float a[4], b[8];
#pragma unroll
                for (int i = 0; i < 4; i++) a[i] = As[ty * 4 + i][k];
#pragma unroll
                for (int j = 0; j < 8; j++) b[j] = Bs[k][tx * 8 + j];
#pragma unroll
                for (int i = 0; i < 4; i++)
#pragma unroll
                    for (int j = 0; j < 8; j++) acc[i][j] = fmaf(a[i], b[j], acc[i][j]);
            }
            __syncthreads();
        }
    }
    // --- epilogue ---
#pragma unroll
    for (int i = 0; i < 4; i++) {
        int gr = row0 + ty * 4 + i;
        if (gr >= N_NODES) continue;
#pragma unroll
        for (int j = 0; j < 8; j += 4) {
            int col = tx * 8 + j;
            float4 v;
            v.x = acc[i][j + 0] + bias[col + 0];
            v.y = acc[i][j + 1] + bias[col + 1];
            v.z = acc[i][j + 2] + bias[col + 2];
            v.w = acc[i][j + 3] + bias[col + 3];
            if (RELU) {
                v.x = fmaxf(v.x, 0.f); v.y = fmaxf(v.y, 0.f);
                v.z = fmaxf(v.z, 0.f); v.w = fmaxf(v.w, 0.f);
            }
            *(float4*)(out + (size_t)gr * HID + col) = v;
        }
    }
}

// ---------------- mean pool (sums + counts via atomics) ----------------
__global__ void pool_kernel(const float* __restrict__ h,
                            const int* __restrict__ batch) {
    // 512 threads = 4 nodes per block
    int n = blockIdx.x * 4 + (threadIdx.x >> 7);
    int t = threadIdx.x & 127;
    if (n >= N_NODES) return;
    int g = batch[n];
    atomicAdd(&g_pool[(size_t)g * HID + t], h[(size_t)n * HID + t]);
    if (t == 0) atomicAdd(&g_cnt[g], 1.f);
}

// ---------------- head: pooled/cnt @ W_lin + b -> sigmoid ----------------
__global__ void head_kernel(const float* __restrict__ Wl,
                            const float* __restrict__ bl,
                            float* __restrict__ out) {
    int g = blockIdx.x;
    int t = threadIdx.x;   // 128
    float c = fmaxf(g_cnt[g], 1.f);
    float v = g_pool[(size_t)g * HID + t] / c * Wl[t];
    __shared__ float red[4];
#pragma unroll
    for (int off = 16; off; off >>= 1) v += __shfl_down_sync(0xffffffffu, v, off);
    if ((t & 31) == 0) red[t >> 5] = v;
    __syncthreads();
    if (t == 0) {
        float s = red[0] + red[1] + red[2] + red[3] + bl[0];
        out[g] = 1.f / (1.f + expf(-s));
    }
}

// ---------------- launch ----------------
extern "C" void kernel_launch(void* const* d_in, const int* in_sizes, int n_in,
                              void* d_out, int out_size) {
    const float* x      = (const float*)d_in[0];
    const int*   ei     = (const int*)d_in[1];
    const int*   batch  = (const int*)d_in[2];
    const float* W_rel0 = (const float*)d_in[3];
    const float* b_rel0 = (const float*)d_in[4];
    const float* W_root0= (const float*)d_in[5];
    const float* W_rel1 = (const float*)d_in[6];
    const float* b_rel1 = (const float*)d_in[7];
    const float* W_root1= (const float*)d_in[8];
    const float* W_rel2 = (const float*)d_in[9];
    const float* b_rel2 = (const float*)d_in[10];
    const float* W_root2= (const float*)d_in[11];
    const float* W_lin  = (const float*)d_in[12];
    const float* b_lin  = (const float*)d_in[13];
    float* out = (float*)d_out;

    float *agg5_p, *agg_p, *pool_p, *cnt_p;
    cudaGetSymbolAddress((void**)&agg5_p, g_agg5);
    cudaGetSymbolAddress((void**)&agg_p,  g_agg);
    cudaGetSymbolAddress((void**)&pool_p, g_pool);
    cudaGetSymbolAddress((void**)&cnt_p,  g_cnt);
    float *h0_p, *h1_p;
    cudaGetSymbolAddress((void**)&h0_p, g_h0);
    cudaGetSymbolAddress((void**)&h1_p, g_h1);

    const size_t aggN4  = (size_t)N_NODES * HID / 4;        // float4 count
    const size_t agg5N4 = (size_t)N_NODES * IN_DIM / 4;     // 62500
    const size_t poolN4 = ((size_t)NUM_GRAPHS * HID + NUM_GRAPHS) / 4 + 1;

    // ---- layer 0 ----
    zero_kernel<<<(unsigned)((agg5N4 + 255) / 256), 256>>>(agg5_p, agg5N4);
    scatter5_kernel<<<(N_EDGES + 255) / 256, 256>>>(x, ei);
    layer0_dense_kernel<<<(N_NODES + 3) / 4, 512>>>(x, W_rel0, b_rel0, W_root0);

    // ---- layer 1 ----
    zero_kernel<<<(unsigned)((aggN4 + 255) / 256), 256>>>(agg_p, aggN4);
    scatter128_kernel<<<(N_EDGES * 32 + 255) / 256, 256>>>(h0_p, ei);
    fused_dense_kernel<1><<<(N_NODES + 63) / 64, 256>>>(agg_p, h0_p, W_rel1, W_root1, b_rel1, h1_p);

    // ---- layer 2 ----
    zero_kernel<<<(unsigned)((aggN4 + 255) / 256), 256>>>(agg_p, aggN4);
    scatter128_kernel<<<(N_EDGES * 32 + 255) / 256, 256>>>(h1_p, ei);
    fused_dense_kernel<0><<<(N_NODES + 63) / 64, 256>>>(agg_p, h1_p, W_rel2, W_root2, b_rel2, h0_p);

    // ---- pool + head ----
    zero_kernel<<<(unsigned)((poolN4 + 255) / 256), 256>>>(pool_p, poolN4);
    // note: g_cnt sits right after g_pool conceptually but is a separate symbol;
    // zero it explicitly (128 floats -> 32 float4)
    zero_kernel<<<1, 128>>>(cnt_p, NUM_GRAPHS / 4);
    pool_kernel<<<(N_NODES + 3) / 4, 512>>>(h0_p, batch);
    head_kernel<<<NUM_GRAPHS, 128>>>(W_lin, b_lin, out);
}

// round 4
// speedup vs baseline: 1.4768x; 1.4768x over previous
#include <cuda_runtime.h>
#include <cuda_bf16.h>
#include <math.h>

#define N_NODES 50000
#define N_EDGES 640000
#define IN_DIM  5
#define HID     128
#define NUM_GRAPHS 512

// ---------------- scratch (no allocations allowed) ----------------
__device__ float g_h0[(size_t)N_NODES * HID];
__device__ float g_h1[(size_t)N_NODES * HID];
__device__ float g_agg[(size_t)N_NODES * HID];
__device__ float g_agg5[(size_t)N_NODES * IN_DIM];
__device__ int   g_deg[N_NODES];
__device__ int   g_rowptr[N_NODES + 1];
__device__ int   g_cursor[N_NODES];
__device__ int   g_csr_src[N_EDGES];
__device__ int   g_start[NUM_GRAPHS + 1];

// ---------------- zero kernel (float4 granularity) ----------------
__global__ void zero_kernel(float* __restrict__ p, size_t n4) {
    size_t i = (size_t)blockIdx.x * blockDim.x + threadIdx.x;
    if (i < n4) ((float4*)p)[i] = make_float4(0.f, 0.f, 0.f, 0.f);
}

// ---------------- CSR build ----------------
__global__ void hist_kernel(const int* __restrict__ ei) {
    int e = blockIdx.x * blockDim.x + threadIdx.x;
    if (e >= N_EDGES) return;
    atomicAdd(&g_deg[ei[N_EDGES + e]], 1);
}

// single-block exclusive scan of g_deg -> g_rowptr (+ cursor copy)
__global__ void scan_kernel() {
    __shared__ int ssum[1024];
    const int t = threadIdx.x;
    const int CH = (N_NODES + 1023) / 1024;       // 49
    int lo = t * CH, hi = min(lo + CH, N_NODES);
    int s = 0;
    for (int i = lo; i < hi; i++) s += g_deg[i];
    ssum[t] = s;
    __syncthreads();
    for (int off = 1; off < 1024; off <<= 1) {
        int v = (t >= off) ? ssum[t - off] : 0;
        __syncthreads();
        ssum[t] += v;
        __syncthreads();
    }
    int run = (t == 0) ? 0 : ssum[t - 1];
    for (int i = lo; i < hi; i++) {
        int d = g_deg[i];
        g_rowptr[i] = run;
        g_cursor[i] = run;
        run += d;
    }
    if (t == 1023) g_rowptr[N_NODES] = run;
}

__global__ void fill_kernel(const int* __restrict__ ei) {
    int e = blockIdx.x * blockDim.x + threadIdx.x;
    if (e >= N_EDGES) return;
    int d = ei[N_EDGES + e];
    int p = atomicAdd(&g_cursor[d], 1);
    g_csr_src[p] = ei[e];
}

// ---------------- layer 0: 5-dim gather ----------------
__global__ void gather5_kernel(const float* __restrict__ x) {
    int node = blockIdx.x * blockDim.x + threadIdx.x;
    if (node >= N_NODES) return;
    int beg = g_rowptr[node], end = g_rowptr[node + 1];
    float a0 = 0.f, a1 = 0.f, a2 = 0.f, a3 = 0.f, a4 = 0.f;
    for (int e = beg; e < end; e++) {
        const float* xs = x + (size_t)g_csr_src[e] * IN_DIM;
        a0 += xs[0]; a1 += xs[1]; a2 += xs[2]; a3 += xs[3]; a4 += xs[4];
    }
    float* o = g_agg5 + (size_t)node * IN_DIM;
    o[0] = a0; o[1] = a1; o[2] = a2; o[3] = a3; o[4] = a4;
}

// ---------------- layer 0: dense (K=5) ----------------
__global__ void layer0_dense_kernel(const float* __restrict__ x,
                                    const float* __restrict__ Wr,
                                    const float* __restrict__ br,
                                    const float* __restrict__ Wt) {
    int n = blockIdx.x * 4 + (threadIdx.x >> 7);
    int o = threadIdx.x & 127;
    if (n >= N_NODES) return;
    float acc = br[o];
#pragma unroll
    for (int i = 0; i < IN_DIM; i++) {
        acc = fmaf(g_agg5[(size_t)n * IN_DIM + i], Wr[i * HID + o], acc);
        acc = fmaf(x[(size_t)n * IN_DIM + i],     Wt[i * HID + o], acc);
    }
    g_h0[(size_t)n * HID + o] = fmaxf(acc, 0.f);
}

// ---------------- 128-dim gather: 1 warp per node, no atomics ----------------
__global__ void gather128_kernel(const float* __restrict__ h) {
    int node = (blockIdx.x * blockDim.x + threadIdx.x) >> 5;
    int lane = threadIdx.x & 31;
    if (node >= N_NODES) return;
    int beg = g_rowptr[node], end = g_rowptr[node + 1];
    float4 acc0 = make_float4(0.f, 0.f, 0.f, 0.f);
    float4 acc1 = make_float4(0.f, 0.f, 0.f, 0.f);
    int e = beg;
    for (; e + 1 < end; e += 2) {
        int s0 = g_csr_src[e];
        int s1 = g_csr_src[e + 1];
        float4 v0 = *(const float4*)(h + (size_t)s0 * HID + lane * 4);
        float4 v1 = *(const float4*)(h + (size_t)s1 * HID + lane * 4);
        acc0.x += v0.x; acc0.y += v0.y; acc0.z += v0.z; acc0.w += v0.w;
        acc1.x += v1.x; acc1.y += v1.y; acc1.z += v1.z; acc1.w += v1.w;
    }
    if (e < end) {
        int s0 = g_csr_src[e];
        float4 v0 = *(const float4*)(h + (size_t)s0 * HID + lane * 4);
        acc0.x += v0.x; acc0.y += v0.y; acc0.z += v0.z; acc0.w += v0.w;
    }
    acc0.x += acc1.x; acc0.y += acc1.y; acc0.z += acc1.z; acc0.w += acc1.w;
    *(float4*)(g_agg + (size_t)node * HID + lane * 4) = acc0;
}

// ---------------- fused dense with FFMA2 (fma.rn.f32x2) ----------------
// out = act(agg@W_rel + h@W_root + b). M=50000, N=128 (split in 2 col blocks
// of 64), K=128 per phase, 2 phases. BM=128, BN=64, BK=16, 256 threads,
// 8x4 micro-tile; f32x2 lanes carry even/odd k partial sums.
__device__ __forceinline__ void ffma2(unsigned long long& d,
                                      unsigned long long a,
                                      unsigned long long b) {
    asm("fma.rn.f32x2 %0, %1, %2, %3;" : "=l"(d) : "l"(a), "l"(b), "l"(d));
}

template <int RELU>
__global__ __launch_bounds__(256)
void fused_dense_kernel(const float* __restrict__ A0,   // agg
                        const float* __restrict__ A1,   // h
                        const float* __restrict__ W0,   // W_rel [128,128]
                        const float* __restrict__ W1,   // W_root [128,128]
                        const float* __restrict__ bias,
                        float* __restrict__ out) {
    __shared__ float As[128][20];   // [row][k]  (rows of A, 16 k's, pad 20)
    __shared__ float Bs[64][20];    // [col][k]  (B transposed)
    const int tid = threadIdx.x;
    const int tx = tid & 15;        // cols: tx + 16*j, j<4 (interleaved)
    const int ty = tid >> 4;        // rows: ty*8 .. ty*8+7
    const int row0 = blockIdx.x * 128;
    const int col0 = blockIdx.y * 64;

    unsigned long long acc[8][4];
#pragma unroll
    for (int i = 0; i < 8; i++)
#pragma unroll
        for (int j = 0; j < 4; j++) acc[i][j] = 0ull;

#pragma unroll
    for (int phase = 0; phase < 2; phase++) {
        const float* A = phase ? A1 : A0;
        const float* W = phase ? W1 : W0;
        for (int k0 = 0; k0 < HID; k0 += 16) {
            // load A tile 128x16: thread -> row tid>>1, col base (tid&1)*8
            {
                int r = tid >> 1;
                int cb = (tid & 1) * 8;
                int gr = row0 + r;
                float4 v0 = make_float4(0.f, 0.f, 0.f, 0.f);
                float4 v1 = v0;
                if (gr < N_NODES) {
                    const float* ap = A + (size_t)gr * HID + k0 + cb;
                    v0 = *(const float4*)ap;
                    v1 = *(const float4*)(ap + 4);
                }
                *(float4*)&As[r][cb]     = v0;
                *(float4*)&As[r][cb + 4] = v1;
            }
            // load B tile 16x64 transposed: thread -> k row tid>>4, cols (tid&15)*4
            {
                int r = tid >> 4;          // 0..15
                int c = (tid & 15) * 4;    // 0..60
                float4 v = *(const float4*)(W + (size_t)(k0 + r) * HID + col0 + c);
                Bs[c + 0][r] = v.x;
                Bs[c + 1][r] = v.y;
                Bs[c + 2][r] = v.z;
                Bs[c + 3][r] = v.w;
            }
            __syncthreads();
#pragma unroll
            for (int kq = 0; kq < 4; kq++) {
                ulonglong2 ap[8], bp[4];
#pragma unroll
                for (int i = 0; i < 8; i++)
                    ap[i] = *(const ulonglong2*)&As[ty * 8 + i][kq * 4];
#pragma unroll
                for (int j = 0; j < 4; j++)
                    bp[j] = *(const ulonglong2*)&Bs[tx + 16 * j][kq * 4];
#pragma unroll
                for (int i = 0; i < 8; i++)
#pragma unroll
                    for (int j = 0; j < 4; j++) {
                        ffma2(acc[i][j], ap[i].x, bp[j].x);
                        ffma2(acc[i][j], ap[i].y, bp[j].y);
                    }
            }
            __syncthreads();
        }
    }
    // epilogue: acc.lo + acc.hi, + bias, act, store
#pragma unroll
    for (int i = 0; i < 8; i++) {
        int gr = row0 + ty * 8 + i;
        if (gr >= N_NODES) continue;
#pragma unroll
        for (int j = 0; j < 4; j++) {
            int c = col0 + tx + 16 * j;
            float lo, hi;
            asm("mov.b64 {%0,%1}, %2;" : "=f"(lo), "=f"(hi) : "l"(acc[i][j]));
            float v = lo + hi + bias[c];
            if (RELU) v = fmaxf(v, 0.f);
            out[(size_t)gr * HID + c] = v;
        }
    }
}

// ---------------- graph segment starts (batch is sorted) ----------------
__global__ void starts_kernel(const int* __restrict__ batch) {
    int g = blockIdx.x * blockDim.x + threadIdx.x;
    if (g > NUM_GRAPHS) return;
    int lo = 0, hi = N_NODES;
    while (lo < hi) {
        int mid = (lo + hi) >> 1;
        if (batch[mid] < g) lo = mid + 1;
        else hi = mid;
    }
    g_start[g] = lo;
}

// ---------------- fused mean-pool + head + sigmoid ----------------
__global__ void pool_head_kernel(const float* __restrict__ h,
                                 const float* __restrict__ Wl,
                                 const float* __restrict__ bl,
                                 float* __restrict__ out) {
    int g = blockIdx.x;
    int t = threadIdx.x;   // 128
    int beg = g_start[g], end = g_start[g + 1];
    float s = 0.f;
    for (int n = beg; n < end; n++) s += h[(size_t)n * HID + t];
    float cnt = fmaxf((float)(end - beg), 1.f);
    float v = (s / cnt) * Wl[t];
    __shared__ float red[4];
#pragma unroll
    for (int off = 16; off; off >>= 1) v += __shfl_down_sync(0xffffffffu, v, off);
    if ((t & 31) == 0) red[t >> 5] = v;
    __syncthreads();
    if (t == 0) {
        float z = red[0] + red[1] + red[2] + red[3] + bl[0];
        out[g] = 1.f / (1.f + expf(-z));
    }
}

// ---------------- launch ----------------
extern "C" void kernel_launch(void* const* d_in, const int* in_sizes, int n_in,
                              void* d_out, int out_size) {
    const float* x      = (const float*)d_in[0];
    const int*   ei     = (const int*)d_in[1];
    const int*   batch  = (const int*)d_in[2];
    const float* W_rel0 = (const float*)d_in[3];
    const float* b_rel0 = (const float*)d_in[4];
    const float* W_root0= (const float*)d_in[5];
    const float* W_rel1 = (const float*)d_in[6];
    const float* b_rel1 = (const float*)d_in[7];
    const float* W_root1= (const float*)d_in[8];
    const float* W_rel2 = (const float*)d_in[9];
    const float* b_rel2 = (const float*)d_in[10];
    const float* W_root2= (const float*)d_in[11];
    const float* W_lin  = (const float*)d_in[12];
    const float* b_lin  = (const float*)d_in[13];
    float* out = (float*)d_out;

    float *deg_p, *agg_p, *h0_p, *h1_p;
    cudaGetSymbolAddress((void**)&deg_p, g_deg);
    cudaGetSymbolAddress((void**)&agg_p, g_agg);
    cudaGetSymbolAddress((void**)&h0_p,  g_h0);
    cudaGetSymbolAddress((void**)&h1_p,  g_h1);

    // ---- CSR build (by dst) ----
    zero_kernel<<<(N_NODES / 4 + 255) / 256, 256>>>(deg_p, N_NODES / 4);
    hist_kernel<<<(N_EDGES + 255) / 256, 256>>>(ei);
    scan_kernel<<<1, 1024>>>();
    fill_kernel<<<(N_EDGES + 255) / 256, 256>>>(ei);

    // ---- graph segment starts (independent) ----
    starts_kernel<<<3, 256>>>(batch);

    // ---- layer 0 ----
    gather5_kernel<<<(N_NODES + 255) / 256, 256>>>(x);
    layer0_dense_kernel<<<(N_NODES + 3) / 4, 512>>>(x, W_rel0, b_rel0, W_root0);

    dim3 dgrid((N_NODES + 127) / 128, 2);

    // ---- layer 1 ----
    gather128_kernel<<<(N_NODES * 32 + 255) / 256, 256>>>(h0_p);
    fused_dense_kernel<1><<<dgrid, 256>>>(agg_p, h0_p, W_rel1, W_root1, b_rel1, h1_p);

    // ---- layer 2 ----
    gather128_kernel<<<(N_NODES * 32 + 255) / 256, 256>>>(h1_p);
    fused_dense_kernel<0><<<dgrid, 256>>>(agg_p, h1_p, W_rel2, W_root2, b_rel2, h0_p);

    // ---- pool + head ----
    pool_head_kernel<<<NUM_GRAPHS, 128>>>(h0_p, W_lin, b_lin, out);
}